// round 3
// baseline (speedup 1.0000x reference)
#include <cuda_runtime.h>
#include <math.h>

#define TT 12
#define NN 20000
#define EE 400000
#define FF 32
#define HH 64
#define GG 256
#define NFUT 4

// ---------------- scratch (device globals; ~170 MB total) ----------------
__device__ int   g_rowptr[NN + 1];
__device__ int   g_cursor[NN];
__device__ int   g_esrc[EE];
__device__ float g_ewt[EE];
__device__ float g_deginv[NN];
__device__ float g_xr[TT * NN * HH];        // relu(emb)            61 MB
__device__ float g_aggx[TT * NN * FF];      // wmean(x)             31 MB
__device__ float g_aggxr[TT * NN * HH];     // wmean(xr)            61 MB
__device__ float g_hbuf[2 * NN * HH];       // ping-pong h
__device__ float g_cb[NN * HH];
__device__ float g_aggh[NN * HH];
__device__ float g_h2s[NFUT * NN * HH];     // layer-2 h, last 4 steps

__device__ __forceinline__ float sigf(float x) { return 1.f / (1.f + expf(-x)); }

// ---------------- CSR build ----------------
__global__ void k_zero_csr() {
    int i = blockIdx.x * 256 + threadIdx.x;
    if (i < NN) g_cursor[i] = 0;
}
__global__ void k_zero_state() {
    int i = blockIdx.x * 256 + threadIdx.x;
    if (i < NN * HH) { g_hbuf[i] = 0.f; g_cb[i] = 0.f; }
}
__global__ void k_hist(const int* __restrict__ ei) {
    int e = blockIdx.x * 256 + threadIdx.x;
    if (e < EE) atomicAdd(&g_cursor[ei[EE + e]], 1);
}
__global__ void k_scan() {
    __shared__ int sh[1024];
    __shared__ int carry_s;
    int tid = threadIdx.x;
    if (tid == 0) { carry_s = 0; g_rowptr[0] = 0; }
    __syncthreads();
    for (int base = 0; base < NN; base += 1024) {
        int i = base + tid;
        int v = (i < NN) ? g_cursor[i] : 0;
        if (i < NN) g_deginv[i] = 1.f / fmaxf((float)v, 1.f);
        sh[tid] = v;
        __syncthreads();
        for (int off = 1; off < 1024; off <<= 1) {
            int t = (tid >= off) ? sh[tid - off] : 0;
            __syncthreads();
            sh[tid] += t;
            __syncthreads();
        }
        int incl = sh[tid];
        int carry = carry_s;
        if (i < NN) {
            g_rowptr[i + 1] = carry + incl;
            g_cursor[i] = carry + incl - v;   // exclusive offset for fill
        }
        __syncthreads();
        if (tid == 1023) carry_s = carry + incl;
        __syncthreads();
    }
}
__global__ void k_fill(const int* __restrict__ ei, const float* __restrict__ ea) {
    int e = blockIdx.x * 256 + threadIdx.x;
    if (e >= EE) return;
    int pos = atomicAdd(&g_cursor[ei[EE + e]], 1);
    g_esrc[pos] = ei[e];
    g_ewt[pos] = ea[e];
}

// ---------------- weighted-mean aggregation via CSR gather ----------------
// One warp per (t,node).
// MODE 0: X = x (D=32) -> g_aggx ; MODE 1: X = g_xr (D=64) -> g_aggxr ;
// MODE 2: X = g_hbuf+hoff (D=64) -> g_aggh.
template <int MODE>
__global__ void k_agg(const float* __restrict__ x_ext, int hoff, int rows) {
    constexpr int D = (MODE == 0) ? 32 : 64;
    const float* __restrict__ X = (MODE == 0) ? x_ext
                                 : (MODE == 1) ? (const float*)g_xr
                                               : (const float*)(g_hbuf + hoff);
    float* __restrict__ out = (MODE == 0) ? g_aggx : (MODE == 1) ? g_aggxr : g_aggh;
    int gw = (blockIdx.x * blockDim.x + threadIdx.x) >> 5;
    int lane = threadIdx.x & 31;
    if (gw >= rows) return;
    int n = gw % NN;
    const float* Xb = X + (size_t)(gw - n) * D;   // t*NN*D base
    int s = g_rowptr[n], e = g_rowptr[n + 1];
    float a0 = 0.f, a1 = 0.f;
    for (int base = s; base < e; base += 32) {
        int idx = base + lane;
        int es = 0; float ew = 0.f;
        if (idx < e) { es = g_esrc[idx]; ew = g_ewt[idx]; }
        int cnt = min(32, e - base);
        for (int j = 0; j < cnt; j++) {
            int sv = __shfl_sync(0xffffffffu, es, j);
            float wv = __shfl_sync(0xffffffffu, ew, j);
            if (D == 64) {
                float2 v = *(const float2*)(Xb + (size_t)sv * 64 + lane * 2);
                a0 += wv * v.x; a1 += wv * v.y;
            } else {
                a0 += wv * Xb[(size_t)sv * 32 + lane];
            }
        }
    }
    float di = g_deginv[n];
    if (D == 64) {
        *(float2*)(out + (size_t)gw * 64 + lane * 2) = make_float2(a0 * di, a1 * di);
    } else {
        out[(size_t)gw * 32 + lane] = a0 * di;
    }
}

// ---------------- SAGE GEMM: emb = aggx@Wr + x@Wroot + b ; xr = relu(emb) ----------------
// BM=128, BN=64, KK=32, TM=8, TN=4, 256 threads.
__global__ void k_sage(const float* __restrict__ x,
                       const float* __restrict__ W1, const float* __restrict__ W2,
                       const float* __restrict__ bias, int M,
                       float* __restrict__ emb) {
    constexpr int BM = 128, BN = 64, KC = 32;
    __shared__ float As[KC][BM + 4];
    __shared__ float Ws[KC][BN];
    const int m0 = blockIdx.x * BM;
    const int tid = threadIdx.x;
    const int tx = tid % 16, ty = tid / 16;   // 16 cols x 16 rows of threads
    float acc[8][4];
#pragma unroll
    for (int i = 0; i < 8; i++)
#pragma unroll
        for (int j = 0; j < 4; j++) acc[i][j] = 0.f;
#pragma unroll 1
    for (int ch = 0; ch < 2; ch++) {
        const float* A = (ch == 0) ? g_aggx : x;
        const float* W = (ch == 0) ? W1 : W2;
#pragma unroll
        for (int l = 0; l < 4; l++) {
            int f = tid + l * 256;
            int m = f >> 3, kq = f & 7;
            int gm = m0 + m; if (gm >= M) gm = M - 1;
            float4 v = *(const float4*)(A + (size_t)gm * 32 + kq * 4);
            As[kq * 4 + 0][m] = v.x; As[kq * 4 + 1][m] = v.y;
            As[kq * 4 + 2][m] = v.z; As[kq * 4 + 3][m] = v.w;
        }
#pragma unroll
        for (int l = 0; l < 2; l++) {
            int f = tid + l * 256;
            int row = f >> 4, c4 = f & 15;
            float4 v = *(const float4*)(W + (size_t)row * 64 + c4 * 4);
            *(float4*)&Ws[row][c4 * 4] = v;
        }
        __syncthreads();
#pragma unroll
        for (int k = 0; k < KC; k++) {
            float av[8], wv[4];
#pragma unroll
            for (int i = 0; i < 8; i += 4) {
                float4 t = *(const float4*)&As[k][ty * 8 + i];
                av[i] = t.x; av[i + 1] = t.y; av[i + 2] = t.z; av[i + 3] = t.w;
            }
            float4 t = *(const float4*)&Ws[k][tx * 4];
            wv[0] = t.x; wv[1] = t.y; wv[2] = t.z; wv[3] = t.w;
#pragma unroll
            for (int i = 0; i < 8; i++)
#pragma unroll
                for (int j = 0; j < 4; j++) acc[i][j] += av[i] * wv[j];
        }
        __syncthreads();
    }
#pragma unroll
    for (int i = 0; i < 8; i++) {
        int r = m0 + ty * 8 + i;
        if (r >= M) continue;
#pragma unroll
        for (int j = 0; j < 4; j++) {
            int c = tx * 4 + j;
            float v = acc[i][j] + bias[c];
            emb[(size_t)r * 64 + c] = v;
            g_xr[(size_t)r * 64 + c] = fmaxf(v, 0.f);
        }
    }
}

// ---------------- fused per-step kernel: full-gate GEMM (K=256) + LSTM pointwise ----------------
// gates = aggxr_t@Wr[0:64] + xr_t@Wroot[0:64] + aggh@Wr[64:128] + h@Wroot[64:128] + b.
// W tiles stored to smem gate-permuted: thread (tx) owns output cols
// {i,f,g,o} x {tx*2, tx*2+1}; smem col s = tx*8 + gate*2 + parity,
// actual col c = gate*64 + tx*2 + parity. Pointwise runs in registers.
__global__ void k_step(int toff, int hin, int hoff_out,
                       const float* __restrict__ Wr, const float* __restrict__ Wroot,
                       const float* __restrict__ bias,
                       int h2off, float* __restrict__ c2dst) {
    __shared__ float As[32][68];
    __shared__ float Ws[32][256];
    const int m0 = blockIdx.x * 64;
    const int tid = threadIdx.x;
    const int tx = tid & 31, ty = tid >> 5;
    float acc[8][8];
#pragma unroll
    for (int i = 0; i < 8; i++)
#pragma unroll
        for (int j = 0; j < 8; j++) acc[i][j] = 0.f;
    // bias, permuted to this thread's columns: j = gate*2 + parity
    float bth[8];
#pragma unroll
    for (int j = 0; j < 8; j++) bth[j] = bias[(j >> 1) * 64 + tx * 2 + (j & 1)];
#pragma unroll 1
    for (int ch = 0; ch < 8; ch++) {
        int pair = ch >> 1;            // 0: aggxr/Wr_top 1: xr/Wroot_top
                                       // 2: aggh/Wr_bot  3: h/Wroot_bot
        int k0 = (ch & 1) * 32;
        const float* A = (pair == 0) ? g_aggxr + toff
                       : (pair == 1) ? g_xr + toff
                       : (pair == 2) ? (const float*)g_aggh
                                     : g_hbuf + hin;
        const float* W = ((pair & 1) ? Wroot : Wr) + (pair >> 1) * 64 * 256;
#pragma unroll
        for (int l = 0; l < 2; l++) {
            int f = tid + l * 256;
            int m = f >> 3, kq = f & 7;
            int gm = m0 + m; if (gm >= NN) gm = NN - 1;
            float4 v = *(const float4*)(A + (size_t)gm * 64 + k0 + kq * 4);
            As[kq * 4 + 0][m] = v.x; As[kq * 4 + 1][m] = v.y;
            As[kq * 4 + 2][m] = v.z; As[kq * 4 + 3][m] = v.w;
        }
#pragma unroll
        for (int l = 0; l < 8; l++) {
            int f = tid + l * 256;
            int row = f >> 6, c4 = f & 63;
            float4 v = *(const float4*)(W + (size_t)(k0 + row) * 256 + c4 * 4);
            float vv[4] = {v.x, v.y, v.z, v.w};
#pragma unroll
            for (int u = 0; u < 4; u++) {
                int c = c4 * 4 + u;
                int s = ((c & 63) >> 1) * 8 + (c >> 6) * 2 + (c & 1);
                Ws[row][s] = vv[u];
            }
        }
        __syncthreads();
#pragma unroll
        for (int k = 0; k < 32; k++) {
            float4 a0 = *(const float4*)&As[k][ty * 8];
            float4 a1 = *(const float4*)&As[k][ty * 8 + 4];
            float4 w0 = *(const float4*)&Ws[k][tx * 8];
            float4 w1 = *(const float4*)&Ws[k][tx * 8 + 4];
            float av[8] = {a0.x, a0.y, a0.z, a0.w, a1.x, a1.y, a1.z, a1.w};
            float wv[8] = {w0.x, w0.y, w0.z, w0.w, w1.x, w1.y, w1.z, w1.w};
#pragma unroll
            for (int i = 0; i < 8; i++)
#pragma unroll
                for (int j = 0; j < 8; j++) acc[i][j] += av[i] * wv[j];
        }
        __syncthreads();
    }
    float* __restrict__ hout = g_hbuf + hoff_out;
#pragma unroll
    for (int i = 0; i < 8; i++) {
        int r = m0 + ty * 8 + i;
        if (r >= NN) continue;
        size_t off = (size_t)r * 64 + tx * 2;
        float2 cv = *(float2*)(g_cb + off);
        float ig0 = acc[i][0] + bth[0], ig1 = acc[i][1] + bth[1];
        float fg0 = acc[i][2] + bth[2], fg1 = acc[i][3] + bth[3];
        float gg0 = acc[i][4] + bth[4], gg1 = acc[i][5] + bth[5];
        float og0 = acc[i][6] + bth[6], og1 = acc[i][7] + bth[7];
        float cn0 = sigf(fg0) * cv.x + sigf(ig0) * tanhf(gg0);
        float cn1 = sigf(fg1) * cv.y + sigf(ig1) * tanhf(gg1);
        float hn0 = sigf(og0) * tanhf(cn0);
        float hn1 = sigf(og1) * tanhf(cn1);
        *(float2*)(g_cb + off) = make_float2(cn0, cn1);
        *(float2*)(hout + off) = make_float2(hn0, hn1);
        if (h2off >= 0) *(float2*)(g_h2s + h2off + off) = make_float2(hn0, hn1);
        if (c2dst) *(float2*)(c2dst + off) = make_float2(cn0, cn1);
    }
}

// ---------------- output head: out = [xr_t, h2] @ W_out + b_out ----------------
__global__ void k_head(const float* __restrict__ Wo, const float* __restrict__ bo,
                       float* __restrict__ out) {
    __shared__ float xs[32][129];
    __shared__ float Wsm[128 * 8];
    __shared__ float bs[8];
    int tid = threadIdx.x;
    for (int i = tid; i < 1024; i += 256) Wsm[i] = Wo[i];
    if (tid < 8) bs[tid] = bo[tid];
    int blk = blockIdx.x;
    int tt = blk / (NN / 32);
    int nb = blk % (NN / 32);
    int n0 = nb * 32;
    int t = TT - NFUT + tt;
    for (int idx = tid; idx < 32 * 128; idx += 256) {
        int r = idx >> 7, k = idx & 127;
        float v = (k < 64)
            ? g_xr[((size_t)t * NN + n0 + r) * 64 + k]
            : g_h2s[((size_t)tt * NN + n0 + r) * 64 + (k - 64)];
        xs[r][k] = v;
    }
    __syncthreads();
    int r = tid >> 3, o = tid & 7;
    float a = bs[o];
    for (int k = 0; k < 128; k++) a += xs[r][k] * Wsm[k * 8 + o];
    out[((size_t)tt * NN + n0 + r) * 8 + o] = a;
}

// ---------------- launch: kernel launches ONLY ----------------
extern "C" void kernel_launch(void* const* d_in, const int* in_sizes, int n_in,
                              void* d_out, int out_size) {
    const float* x      = (const float*)d_in[0];
    const int*   ei     = (const int*)d_in[1];
    const float* ea     = (const float*)d_in[2];
    const float* sWr    = (const float*)d_in[3];
    const float* sWroot = (const float*)d_in[4];
    const float* sb     = (const float*)d_in[5];
    const float* l1Wr   = (const float*)d_in[6];
    const float* l1Wrt  = (const float*)d_in[7];
    const float* l1b    = (const float*)d_in[8];
    const float* l2Wr   = (const float*)d_in[9];
    const float* l2Wrt  = (const float*)d_in[10];
    const float* l2b    = (const float*)d_in[11];
    const float* Wo     = (const float*)d_in[12];
    const float* bo     = (const float*)d_in[13];

    float* out_pred = (float*)d_out;                 // [4,N,8]
    float* out_c2   = out_pred + NFUT * NN * 8;      // [N,64]
    float* out_emb  = out_c2 + NN * HH;              // [T,N,64]

    // CSR build
    k_zero_csr<<<(NN + 255) / 256, 256>>>();
    k_hist<<<(EE + 255) / 256, 256>>>(ei);
    k_scan<<<1, 1024>>>();
    k_fill<<<(EE + 255) / 256, 256>>>(ei, ea);

    // SAGE: agg(x); emb = aggx@Wr + x@Wroot + b ; xr = relu(emb)
    k_agg<0><<<TT * NN / 8, 256>>>(x, 0, TT * NN);
    k_sage<<<(TT * NN + 127) / 128, 256>>>(x, sWr, sWroot, sb, TT * NN, out_emb);

    // shared aggregation of xr (used by both LSTM layers, all timesteps)
    k_agg<1><<<TT * NN / 8, 256>>>(nullptr, 0, TT * NN);

    // h0 = c0 = 0
    k_zero_state<<<(NN * HH + 255) / 256, 256>>>();

    const int stepBlocks = (NN + 63) / 64;
    int cur = 0;
    // layer 1
    for (int t = 0; t < TT; t++) {
        k_agg<2><<<NN / 8, 256>>>(nullptr, cur * NN * HH, NN);
        k_step<<<stepBlocks, 256>>>(
            t * NN * HH, cur * NN * HH, (1 - cur) * NN * HH,
            l1Wr, l1Wrt, l1b, -1, nullptr);
        cur ^= 1;
    }
    // layer 2 (state carries over: h = h1[-1], c = c1)
    for (int t = 0; t < TT; t++) {
        k_agg<2><<<NN / 8, 256>>>(nullptr, cur * NN * HH, NN);
        int h2off = (t >= TT - NFUT) ? (t - (TT - NFUT)) * NN * HH : -1;
        float* c2d = (t == TT - 1) ? out_c2 : nullptr;
        k_step<<<stepBlocks, 256>>>(
            t * NN * HH, cur * NN * HH, (1 - cur) * NN * HH,
            l2Wr, l2Wrt, l2b, h2off, c2d);
        cur ^= 1;
    }

    // output head
    k_head<<<NFUT * NN / 32, 256>>>(Wo, bo, out_pred);
}

// round 4
// speedup vs baseline: 1.9654x; 1.9654x over previous
#include <cuda_runtime.h>
#include <math.h>

#define TT 12
#define NN 20000
#define EE 400000
#define FF 32
#define HH 64
#define GG 256
#define NFUT 4

// ---------------- scratch (device globals; ~170 MB total) ----------------
__device__ int   g_rowptr[NN + 1];
__device__ int   g_cursor[NN];
__device__ int   g_esrc[EE];
__device__ float g_ewt[EE];
__device__ float g_deginv[NN];
__device__ float g_xr[TT * NN * HH];        // relu(emb)
__device__ float g_aggx[TT * NN * FF];      // wmean(x)
__device__ float g_aggxr[TT * NN * HH];     // wmean(xr)
__device__ float g_hbuf[2 * NN * HH];       // ping-pong h
__device__ float g_cb[NN * HH];
__device__ float g_aggh[NN * HH];
__device__ float g_h2s[NFUT * NN * HH];     // layer-2 h, last 4 steps

__device__ __forceinline__ float sigf(float x) { return 1.f / (1.f + expf(-x)); }

__device__ __forceinline__ unsigned tf32_bits(float x) {
    unsigned u;
    asm("cvt.rna.tf32.f32 %0, %1;" : "=r"(u) : "f"(x));
    return u;
}
__device__ __forceinline__ float tf32f(float x) {
    return __uint_as_float(tf32_bits(x));
}

// ---------------- CSR build ----------------
__global__ void k_zero_csr() {
    int i = blockIdx.x * 256 + threadIdx.x;
    if (i < NN) g_cursor[i] = 0;
}
__global__ void k_zero_state() {
    int i = blockIdx.x * 256 + threadIdx.x;
    if (i < NN * HH) { g_hbuf[i] = 0.f; g_cb[i] = 0.f; }
}
__global__ void k_hist(const int* __restrict__ ei) {
    int e = blockIdx.x * 256 + threadIdx.x;
    if (e < EE) atomicAdd(&g_cursor[ei[EE + e]], 1);
}
__global__ void k_scan() {
    __shared__ int sh[1024];
    __shared__ int carry_s;
    int tid = threadIdx.x;
    if (tid == 0) { carry_s = 0; g_rowptr[0] = 0; }
    __syncthreads();
    for (int base = 0; base < NN; base += 1024) {
        int i = base + tid;
        int v = (i < NN) ? g_cursor[i] : 0;
        if (i < NN) g_deginv[i] = 1.f / fmaxf((float)v, 1.f);
        sh[tid] = v;
        __syncthreads();
        for (int off = 1; off < 1024; off <<= 1) {
            int t = (tid >= off) ? sh[tid - off] : 0;
            __syncthreads();
            sh[tid] += t;
            __syncthreads();
        }
        int incl = sh[tid];
        int carry = carry_s;
        if (i < NN) {
            g_rowptr[i + 1] = carry + incl;
            g_cursor[i] = carry + incl - v;   // exclusive offset for fill
        }
        __syncthreads();
        if (tid == 1023) carry_s = carry + incl;
        __syncthreads();
    }
}
__global__ void k_fill(const int* __restrict__ ei, const float* __restrict__ ea) {
    int e = blockIdx.x * 256 + threadIdx.x;
    if (e >= EE) return;
    int pos = atomicAdd(&g_cursor[ei[EE + e]], 1);
    g_esrc[pos] = ei[e];
    g_ewt[pos] = ea[e];
}

// ---------------- weighted-mean aggregation via CSR gather ----------------
template <int MODE>
__global__ void k_agg(const float* __restrict__ x_ext, int hoff, int rows) {
    constexpr int D = (MODE == 0) ? 32 : 64;
    const float* __restrict__ X = (MODE == 0) ? x_ext
                                 : (MODE == 1) ? (const float*)g_xr
                                               : (const float*)(g_hbuf + hoff);
    float* __restrict__ out = (MODE == 0) ? g_aggx : (MODE == 1) ? g_aggxr : g_aggh;
    int gw = (blockIdx.x * blockDim.x + threadIdx.x) >> 5;
    int lane = threadIdx.x & 31;
    if (gw >= rows) return;
    int n = gw % NN;
    const float* Xb = X + (size_t)(gw - n) * D;   // t*NN*D base
    int s = g_rowptr[n], e = g_rowptr[n + 1];
    float a0 = 0.f, a1 = 0.f;
    for (int base = s; base < e; base += 32) {
        int idx = base + lane;
        int es = 0; float ew = 0.f;
        if (idx < e) { es = g_esrc[idx]; ew = g_ewt[idx]; }
        int cnt = min(32, e - base);
        for (int j = 0; j < cnt; j++) {
            int sv = __shfl_sync(0xffffffffu, es, j);
            float wv = __shfl_sync(0xffffffffu, ew, j);
            if (D == 64) {
                float2 v = *(const float2*)(Xb + (size_t)sv * 64 + lane * 2);
                a0 += wv * v.x; a1 += wv * v.y;
            } else {
                a0 += wv * Xb[(size_t)sv * 32 + lane];
            }
        }
    }
    float di = g_deginv[n];
    if (D == 64) {
        *(float2*)(out + (size_t)gw * 64 + lane * 2) = make_float2(a0 * di, a1 * di);
    } else {
        out[(size_t)gw * 32 + lane] = a0 * di;
    }
}

// ---------------- SAGE GEMM (fp32 FFMA; emb is an output, keep exact) ----------------
__global__ void k_sage(const float* __restrict__ x,
                       const float* __restrict__ W1, const float* __restrict__ W2,
                       const float* __restrict__ bias, int M,
                       float* __restrict__ emb) {
    constexpr int BM = 128, KC = 32;
    __shared__ float As[KC][BM + 4];
    __shared__ float Ws[KC][64];
    const int m0 = blockIdx.x * BM;
    const int tid = threadIdx.x;
    const int tx = tid % 16, ty = tid / 16;
    float acc[8][4];
#pragma unroll
    for (int i = 0; i < 8; i++)
#pragma unroll
        for (int j = 0; j < 4; j++) acc[i][j] = 0.f;
#pragma unroll 1
    for (int ch = 0; ch < 2; ch++) {
        const float* A = (ch == 0) ? g_aggx : x;
        const float* W = (ch == 0) ? W1 : W2;
#pragma unroll
        for (int l = 0; l < 4; l++) {
            int f = tid + l * 256;
            int m = f >> 3, kq = f & 7;
            int gm = m0 + m; if (gm >= M) gm = M - 1;
            float4 v = *(const float4*)(A + (size_t)gm * 32 + kq * 4);
            As[kq * 4 + 0][m] = v.x; As[kq * 4 + 1][m] = v.y;
            As[kq * 4 + 2][m] = v.z; As[kq * 4 + 3][m] = v.w;
        }
#pragma unroll
        for (int l = 0; l < 2; l++) {
            int f = tid + l * 256;
            int row = f >> 4, c4 = f & 15;
            float4 v = *(const float4*)(W + (size_t)row * 64 + c4 * 4);
            *(float4*)&Ws[row][c4 * 4] = v;
        }
        __syncthreads();
#pragma unroll
        for (int k = 0; k < KC; k++) {
            float av[8], wv[4];
#pragma unroll
            for (int i = 0; i < 8; i += 4) {
                float4 t = *(const float4*)&As[k][ty * 8 + i];
                av[i] = t.x; av[i + 1] = t.y; av[i + 2] = t.z; av[i + 3] = t.w;
            }
            float4 t = *(const float4*)&Ws[k][tx * 4];
            wv[0] = t.x; wv[1] = t.y; wv[2] = t.z; wv[3] = t.w;
#pragma unroll
            for (int i = 0; i < 8; i++)
#pragma unroll
                for (int j = 0; j < 4; j++) acc[i][j] += av[i] * wv[j];
        }
        __syncthreads();
    }
#pragma unroll
    for (int i = 0; i < 8; i++) {
        int r = m0 + ty * 8 + i;
        if (r >= M) continue;
#pragma unroll
        for (int j = 0; j < 4; j++) {
            int c = tx * 4 + j;
            float v = acc[i][j] + bias[c];
            emb[(size_t)r * 64 + c] = v;
            g_xr[(size_t)r * 64 + c] = fmaxf(v, 0.f);
        }
    }
}

// ---------------- fused per-step: tf32 tensor-core gate GEMM + LSTM pointwise ----------------
// gates = aggxr_t@Wr[0:64] + xr_t@Wroot[0:64] + aggh@Wr[64:128] + h@Wroot[64:128] + b.
// 8 warps: warps 0-3 -> rows (w&3)*16, cols 0..127 (gates i,f, kept in regs);
// warps 4-7 -> same rows, cols 128..255 (gates g,o, staged to smem overlay).
__global__ void __launch_bounds__(256) k_step(
        int toff, int hin, int hoff_out,
        const float* __restrict__ Wr, const float* __restrict__ Wroot,
        const float* __restrict__ bias,
        int h2off, float* __restrict__ c2dst) {
    __shared__ float As[64][36];     // m-major A tile (tf32 bits), conflict-free frag loads
    __shared__ float Ws[32][264];    // k-major W tile; overlaid by gate staging later
    float (*gsm)[132] = (float(*)[132])&Ws[0][0];   // 64 x 132 overlay (33792 B, == Ws)

    const int m0 = blockIdx.x * 64;
    const int tid = threadIdx.x;
    const int w = tid >> 5, lane = tid & 31;
    const int M0 = (w & 3) * 16;
    const int ncolbase = (w >> 2) * 128 + (lane >> 2);
    const int lr = lane >> 2, lc = lane & 3;

    float acc[16][4];
#pragma unroll
    for (int i = 0; i < 16; i++)
#pragma unroll
        for (int j = 0; j < 4; j++) acc[i][j] = 0.f;

#pragma unroll 1
    for (int ch = 0; ch < 8; ch++) {
        int pair = ch >> 1;
        int k0g = (ch & 1) * 32;
        const float* A = (pair == 0) ? g_aggxr + toff
                       : (pair == 1) ? g_xr + toff
                       : (pair == 2) ? (const float*)g_aggh
                                     : g_hbuf + hin;
        const float* W = ((pair & 1) ? Wroot : Wr) + (pair >> 1) * 64 * 256;
        // stage A: 64 x 32 (2 float4 per thread), convert to tf32
#pragma unroll
        for (int l = 0; l < 2; l++) {
            int f = tid + l * 256;
            int m = f >> 3, kq = f & 7;
            int gm = m0 + m; if (gm >= NN) gm = NN - 1;
            float4 v = *(const float4*)(A + (size_t)gm * 64 + k0g + kq * 4);
            float4 c4v = make_float4(tf32f(v.x), tf32f(v.y), tf32f(v.z), tf32f(v.w));
            *(float4*)&As[m][kq * 4] = c4v;
        }
        // stage W: 32 x 256 (8 float4 per thread), convert to tf32
#pragma unroll
        for (int l = 0; l < 8; l++) {
            int f = tid + l * 256;
            int row = f >> 6, c4 = f & 63;
            float4 v = *(const float4*)(W + (size_t)(k0g + row) * 256 + c4 * 4);
            float4 c4v = make_float4(tf32f(v.x), tf32f(v.y), tf32f(v.z), tf32f(v.w));
            *(float4*)&Ws[row][c4 * 4] = c4v;
        }
        __syncthreads();
#pragma unroll
        for (int k0 = 0; k0 < 32; k0 += 8) {
            unsigned a0 = __float_as_uint(As[M0 + lr][k0 + lc]);
            unsigned a1 = __float_as_uint(As[M0 + lr + 8][k0 + lc]);
            unsigned a2 = __float_as_uint(As[M0 + lr][k0 + lc + 4]);
            unsigned a3 = __float_as_uint(As[M0 + lr + 8][k0 + lc + 4]);
#pragma unroll
            for (int nt = 0; nt < 16; nt++) {
                int n = ncolbase + nt * 8;
                unsigned b0 = __float_as_uint(Ws[k0 + lc][n]);
                unsigned b1 = __float_as_uint(Ws[k0 + 4 + lc][n]);
                asm volatile(
                    "mma.sync.aligned.m16n8k8.row.col.f32.tf32.tf32.f32 "
                    "{%0,%1,%2,%3}, {%4,%5,%6,%7}, {%8,%9}, {%0,%1,%2,%3};"
                    : "+f"(acc[nt][0]), "+f"(acc[nt][1]), "+f"(acc[nt][2]), "+f"(acc[nt][3])
                    : "r"(a0), "r"(a1), "r"(a2), "r"(a3), "r"(b0), "r"(b1));
            }
        }
        __syncthreads();
    }

    // warps 4-7: stage gates g,o (+bias) into smem overlay
    if (w >= 4) {
#pragma unroll
        for (int nt = 0; nt < 16; nt++) {
            int bcol = 128 + nt * 8 + lc * 2;                  // global gate column
            int gcol = (nt & 7) * 8 + lc * 2 + ((nt >> 3) * 64);
            float b0 = bias[bcol], b1 = bias[bcol + 1];
            gsm[M0 + lr][gcol]     = acc[nt][0] + b0;
            gsm[M0 + lr][gcol + 1] = acc[nt][1] + b1;
            gsm[M0 + lr + 8][gcol]     = acc[nt][2] + b0;
            gsm[M0 + lr + 8][gcol + 1] = acc[nt][3] + b1;
        }
    }
    __syncthreads();

    // warps 0-3: pointwise LSTM update (i,f from regs; g,o from smem)
    if (w < 4) {
        float* __restrict__ hout = g_hbuf + hoff_out;
#pragma unroll
        for (int half = 0; half < 2; half++) {
            int lrr = M0 + lr + half * 8;
            int r = m0 + lrr;
            if (r >= NN) continue;
#pragma unroll
            for (int nt = 0; nt < 8; nt++) {
                int c = nt * 8 + lc * 2;
                float i0 = acc[nt][half * 2 + 0] + bias[c];
                float i1 = acc[nt][half * 2 + 1] + bias[c + 1];
                float f0 = acc[nt + 8][half * 2 + 0] + bias[64 + c];
                float f1 = acc[nt + 8][half * 2 + 1] + bias[64 + c + 1];
                float2 gv = *(float2*)&gsm[lrr][c];
                float2 ov = *(float2*)&gsm[lrr][c + 64];
                size_t off = (size_t)r * 64 + c;
                float2 cv = *(float2*)(g_cb + off);
                float cn0 = sigf(f0) * cv.x + sigf(i0) * tanhf(gv.x);
                float cn1 = sigf(f1) * cv.y + sigf(i1) * tanhf(gv.y);
                float hn0 = sigf(ov.x) * tanhf(cn0);
                float hn1 = sigf(ov.y) * tanhf(cn1);
                *(float2*)(g_cb + off) = make_float2(cn0, cn1);
                *(float2*)(hout + off) = make_float2(hn0, hn1);
                if (h2off >= 0) *(float2*)(g_h2s + h2off + off) = make_float2(hn0, hn1);
                if (c2dst) *(float2*)(c2dst + off) = make_float2(cn0, cn1);
            }
        }
    }
}

// ---------------- output head: out = [xr_t, h2] @ W_out + b_out ----------------
__global__ void k_head(const float* __restrict__ Wo, const float* __restrict__ bo,
                       float* __restrict__ out) {
    __shared__ float xs[32][129];
    __shared__ float Wsm[128 * 8];
    __shared__ float bs[8];
    int tid = threadIdx.x;
    for (int i = tid; i < 1024; i += 256) Wsm[i] = Wo[i];
    if (tid < 8) bs[tid] = bo[tid];
    int blk = blockIdx.x;
    int tt = blk / (NN / 32);
    int nb = blk % (NN / 32);
    int n0 = nb * 32;
    int t = TT - NFUT + tt;
    for (int idx = tid; idx < 32 * 128; idx += 256) {
        int r = idx >> 7, k = idx & 127;
        float v = (k < 64)
            ? g_xr[((size_t)t * NN + n0 + r) * 64 + k]
            : g_h2s[((size_t)tt * NN + n0 + r) * 64 + (k - 64)];
        xs[r][k] = v;
    }
    __syncthreads();
    int r = tid >> 3, o = tid & 7;
    float a = bs[o];
    for (int k = 0; k < 128; k++) a += xs[r][k] * Wsm[k * 8 + o];
    out[((size_t)tt * NN + n0 + r) * 8 + o] = a;
}

// ---------------- launch: kernel launches ONLY ----------------
extern "C" void kernel_launch(void* const* d_in, const int* in_sizes, int n_in,
                              void* d_out, int out_size) {
    const float* x      = (const float*)d_in[0];
    const int*   ei     = (const int*)d_in[1];
    const float* ea     = (const float*)d_in[2];
    const float* sWr    = (const float*)d_in[3];
    const float* sWroot = (const float*)d_in[4];
    const float* sb     = (const float*)d_in[5];
    const float* l1Wr   = (const float*)d_in[6];
    const float* l1Wrt  = (const float*)d_in[7];
    const float* l1b    = (const float*)d_in[8];
    const float* l2Wr   = (const float*)d_in[9];
    const float* l2Wrt  = (const float*)d_in[10];
    const float* l2b    = (const float*)d_in[11];
    const float* Wo     = (const float*)d_in[12];
    const float* bo     = (const float*)d_in[13];

    float* out_pred = (float*)d_out;                 // [4,N,8]
    float* out_c2   = out_pred + NFUT * NN * 8;      // [N,64]
    float* out_emb  = out_c2 + NN * HH;              // [T,N,64]

    // CSR build
    k_zero_csr<<<(NN + 255) / 256, 256>>>();
    k_hist<<<(EE + 255) / 256, 256>>>(ei);
    k_scan<<<1, 1024>>>();
    k_fill<<<(EE + 255) / 256, 256>>>(ei, ea);

    // SAGE: agg(x); emb = aggx@Wr + x@Wroot + b ; xr = relu(emb)
    k_agg<0><<<TT * NN / 8, 256>>>(x, 0, TT * NN);
    k_sage<<<(TT * NN + 127) / 128, 256>>>(x, sWr, sWroot, sb, TT * NN, out_emb);

    // shared aggregation of xr (used by both LSTM layers, all timesteps)
    k_agg<1><<<TT * NN / 8, 256>>>(nullptr, 0, TT * NN);

    // h0 = c0 = 0
    k_zero_state<<<(NN * HH + 255) / 256, 256>>>();

    const int stepBlocks = (NN + 63) / 64;
    int cur = 0;
    // layer 1
    for (int t = 0; t < TT; t++) {
        k_agg<2><<<NN / 8, 256>>>(nullptr, cur * NN * HH, NN);
        k_step<<<stepBlocks, 256>>>(
            t * NN * HH, cur * NN * HH, (1 - cur) * NN * HH,
            l1Wr, l1Wrt, l1b, -1, nullptr);
        cur ^= 1;
    }
    // layer 2 (state carries over: h = h1[-1], c = c1)
    for (int t = 0; t < TT; t++) {
        k_agg<2><<<NN / 8, 256>>>(nullptr, cur * NN * HH, NN);
        int h2off = (t >= TT - NFUT) ? (t - (TT - NFUT)) * NN * HH : -1;
        float* c2d = (t == TT - 1) ? out_c2 : nullptr;
        k_step<<<stepBlocks, 256>>>(
            t * NN * HH, cur * NN * HH, (1 - cur) * NN * HH,
            l2Wr, l2Wrt, l2b, h2off, c2d);
        cur ^= 1;
    }

    // output head
    k_head<<<NFUT * NN / 32, 256>>>(Wo, bo, out_pred);
}